// round 1
// baseline (speedup 1.0000x reference)
#include <cuda_runtime.h>

#define BB 8
#define CC 3
#define HH 512
#define WW 1024
#define HWN (HH * WW)
#define NN (BB * HWN)
#define SAME_RANGE 0.2f

// Scratch (allocation-free): z-buffer (depth bits) and splat counts.
__device__ unsigned int g_dlut[NN];
__device__ float g_cnt[NN];

// Compute the flat target index for source pixel i. Matches reference:
// p1 = grid + flow; clip to [0, dim-1]; round-half-even; idx = b*HW + yi*W + xi.
__device__ __forceinline__ int target_index(int i, const float* __restrict__ flow) {
    int b = i / HWN;
    int p = i - b * HWN;
    int y = p >> 10;          // p / WW  (WW = 1024)
    int x = p & (WW - 1);     // p % WW
    const float* fb = flow + (size_t)b * 2 * HWN;
    float px = (float)x + fb[p];
    float py = (float)y + fb[HWN + p];
    px = fminf(fmaxf(px, 0.0f), (float)(WW - 1));
    py = fminf(fmaxf(py, 0.0f), (float)(HH - 1));
    int xi = (int)rintf(px);  // round-to-nearest-even, matches jnp.round
    int yi = (int)rintf(py);
    return b * HWN + yi * WW + xi;
}

__global__ void zmin_kernel(const float* __restrict__ flow,
                            const float* __restrict__ depth) {
    int i = blockIdx.x * blockDim.x + threadIdx.x;
    if (i >= NN) return;
    int t = target_index(i, flow);
    // depth in [0,1): non-negative float => uint bit order == float order
    atomicMin(&g_dlut[t], __float_as_uint(depth[i]));
}

__global__ void splat_kernel(const float* __restrict__ obj,
                             const float* __restrict__ flow,
                             const float* __restrict__ depth,
                             float* __restrict__ out) {
    int i = blockIdx.x * blockDim.x + threadIdx.x;
    if (i >= NN) return;
    int t = target_index(i, flow);
    float d = depth[i];
    float dmin = __uint_as_float(g_dlut[t]);
    if (d <= dmin + SAME_RANGE) {
        int b = i / HWN;
        int p = i - b * HWN;
        int tl = t - b * HWN;
        const float* ob = obj + (size_t)b * CC * HWN;
        float* outb = out + (size_t)b * CC * HWN;
        atomicAdd(&g_cnt[t], 1.0f);
        atomicAdd(&outb[0 * HWN + tl], ob[0 * HWN + p]);
        atomicAdd(&outb[1 * HWN + tl], ob[1 * HWN + p]);
        atomicAdd(&outb[2 * HWN + tl], ob[2 * HWN + p]);
    }
}

__global__ void normalize_kernel(float* __restrict__ out) {
    int t = blockIdx.x * blockDim.x + threadIdx.x;
    if (t >= NN) return;
    float c = g_cnt[t];
    if (c > 0.0f) {
        int b = t / HWN;
        int tl = t - b * HWN;
        float* outb = out + (size_t)b * CC * HWN;
        outb[0 * HWN + tl] = outb[0 * HWN + tl] / c;
        outb[1 * HWN + tl] = outb[1 * HWN + tl] / c;
        outb[2 * HWN + tl] = outb[2 * HWN + tl] / c;
    }
    // c == 0: out stays 0 from the memset (matches reference's jnp.where(..., 0))
}

extern "C" void kernel_launch(void* const* d_in, const int* in_sizes, int n_in,
                              void* d_out, int out_size) {
    const float* obj   = (const float*)d_in[0];
    const float* flow  = (const float*)d_in[1];
    const float* depth = (const float*)d_in[2];
    float* out = (float*)d_out;

    void* dlut_ptr = nullptr;
    void* cnt_ptr  = nullptr;
    cudaGetSymbolAddress(&dlut_ptr, g_dlut);
    cudaGetSymbolAddress(&cnt_ptr, g_cnt);

    // dlut -> 0x7F7F7F7F (huge positive float bits), cnt -> 0, out -> 0
    cudaMemsetAsync(dlut_ptr, 0x7F, (size_t)NN * sizeof(unsigned int), 0);
    cudaMemsetAsync(cnt_ptr, 0, (size_t)NN * sizeof(float), 0);
    cudaMemsetAsync(out, 0, (size_t)NN * CC * sizeof(float), 0);

    const int TPB = 256;
    const int blocks = (NN + TPB - 1) / TPB;
    zmin_kernel<<<blocks, TPB, 0, 0>>>(flow, depth);
    splat_kernel<<<blocks, TPB, 0, 0>>>(obj, flow, depth, out);
    normalize_kernel<<<blocks, TPB, 0, 0>>>(out);
}

// round 2
// speedup vs baseline: 1.2284x; 1.2284x over previous
#include <cuda_runtime.h>

#define HWN (512 * 1024)   // 2^19 per-batch pixels
#define NN  (8 * HWN)
#define SAME_RANGE 0.2f

// Scratch (allocation-free):
// g_acc[t] = (sum_c0, sum_c1, sum_c2, count) accumulated with one v4 RED.
// g_dlut[t] = min depth bits (unsigned; depth in [0,1) so bit order == float order).
__device__ float4 g_acc[NN];          // 64MB
__device__ unsigned int g_dlut[NN];   // 16MB

__device__ __forceinline__ void targets4(int i, const float* __restrict__ flow,
                                         int4& t) {
    // i = base pixel index, multiple of 4; 4 consecutive pixels share a row
    int b = i >> 22;               // i / NN-per-batch? no: per-batch = 2^19*... careful below
    // NOTE: i indexes global pixels [0, NN); batch = i >> 19? NN per batch = HWN = 2^19.
    b = i >> 19;
    int p = i & (HWN - 1);
    int y = p >> 10;
    int x = p & 1023;
    const float* fb = flow + (size_t)b * 2 * HWN;
    float4 fx = *reinterpret_cast<const float4*>(fb + p);
    float4 fy = *reinterpret_cast<const float4*>(fb + HWN + p);
    float yf = (float)y;

    float px0 = fminf(fmaxf((float)(x + 0) + fx.x, 0.0f), 1023.0f);
    float px1 = fminf(fmaxf((float)(x + 1) + fx.y, 0.0f), 1023.0f);
    float px2 = fminf(fmaxf((float)(x + 2) + fx.z, 0.0f), 1023.0f);
    float px3 = fminf(fmaxf((float)(x + 3) + fx.w, 0.0f), 1023.0f);
    float py0 = fminf(fmaxf(yf + fy.x, 0.0f), 511.0f);
    float py1 = fminf(fmaxf(yf + fy.y, 0.0f), 511.0f);
    float py2 = fminf(fmaxf(yf + fy.z, 0.0f), 511.0f);
    float py3 = fminf(fmaxf(yf + fy.w, 0.0f), 511.0f);

    int base = b << 19;
    t.x = base + ((int)rintf(py0) << 10) + (int)rintf(px0);
    t.y = base + ((int)rintf(py1) << 10) + (int)rintf(px1);
    t.z = base + ((int)rintf(py2) << 10) + (int)rintf(px2);
    t.w = base + ((int)rintf(py3) << 10) + (int)rintf(px3);
}

__global__ void zmin_kernel(const float* __restrict__ flow,
                            const float* __restrict__ depth) {
    int i = (blockIdx.x * blockDim.x + threadIdx.x) << 2;
    int4 t;
    targets4(i, flow, t);
    float4 d = *reinterpret_cast<const float4*>(depth + i);
    atomicMin(&g_dlut[t.x], __float_as_uint(d.x));
    atomicMin(&g_dlut[t.y], __float_as_uint(d.y));
    atomicMin(&g_dlut[t.z], __float_as_uint(d.z));
    atomicMin(&g_dlut[t.w], __float_as_uint(d.w));
}

__device__ __forceinline__ void red_add_v4(float4* p, float a, float b, float c, float d) {
    asm volatile("red.global.add.v4.f32 [%0], {%1, %2, %3, %4};"
                 :: "l"(p), "f"(a), "f"(b), "f"(c), "f"(d) : "memory");
}

__global__ void splat_kernel(const float* __restrict__ obj,
                             const float* __restrict__ flow,
                             const float* __restrict__ depth) {
    int i = (blockIdx.x * blockDim.x + threadIdx.x) << 2;
    int4 t;
    targets4(i, flow, t);
    float4 d = *reinterpret_cast<const float4*>(depth + i);

    // gather the per-target minima
    float m0 = __uint_as_float(g_dlut[t.x]) + SAME_RANGE;
    float m1 = __uint_as_float(g_dlut[t.y]) + SAME_RANGE;
    float m2 = __uint_as_float(g_dlut[t.z]) + SAME_RANGE;
    float m3 = __uint_as_float(g_dlut[t.w]) + SAME_RANGE;

    int b = i >> 19;
    int p = i & (HWN - 1);
    const float* ob = obj + (size_t)b * 3 * HWN;
    float4 o0 = *reinterpret_cast<const float4*>(ob + 0 * HWN + p);
    float4 o1 = *reinterpret_cast<const float4*>(ob + 1 * HWN + p);
    float4 o2 = *reinterpret_cast<const float4*>(ob + 2 * HWN + p);

    if (d.x <= m0) red_add_v4(&g_acc[t.x], o0.x, o1.x, o2.x, 1.0f);
    if (d.y <= m1) red_add_v4(&g_acc[t.y], o0.y, o1.y, o2.y, 1.0f);
    if (d.z <= m2) red_add_v4(&g_acc[t.z], o0.z, o1.z, o2.z, 1.0f);
    if (d.w <= m3) red_add_v4(&g_acc[t.w], o0.w, o1.w, o2.w, 1.0f);
}

__global__ void normalize_kernel(float* __restrict__ out) {
    int i = (blockIdx.x * blockDim.x + threadIdx.x) << 2;
    int b = i >> 19;
    int p = i & (HWN - 1);

    float4 a0 = g_acc[i + 0];
    float4 a1 = g_acc[i + 1];
    float4 a2 = g_acc[i + 2];
    float4 a3 = g_acc[i + 3];

    float r0 = a0.w > 0.0f ? __fdividef(1.0f, a0.w) : 0.0f;
    float r1 = a1.w > 0.0f ? __fdividef(1.0f, a1.w) : 0.0f;
    float r2 = a2.w > 0.0f ? __fdividef(1.0f, a2.w) : 0.0f;
    float r3 = a3.w > 0.0f ? __fdividef(1.0f, a3.w) : 0.0f;

    float4 c0 = make_float4(a0.x * r0, a1.x * r1, a2.x * r2, a3.x * r3);
    float4 c1 = make_float4(a0.y * r0, a1.y * r1, a2.y * r2, a3.y * r3);
    float4 c2 = make_float4(a0.z * r0, a1.z * r1, a2.z * r2, a3.z * r3);

    float* outb = out + (size_t)b * 3 * HWN;
    *reinterpret_cast<float4*>(outb + 0 * HWN + p) = c0;
    *reinterpret_cast<float4*>(outb + 1 * HWN + p) = c1;
    *reinterpret_cast<float4*>(outb + 2 * HWN + p) = c2;
}

extern "C" void kernel_launch(void* const* d_in, const int* in_sizes, int n_in,
                              void* d_out, int out_size) {
    const float* obj   = (const float*)d_in[0];
    const float* flow  = (const float*)d_in[1];
    const float* depth = (const float*)d_in[2];
    float* out = (float*)d_out;

    void* acc_ptr = nullptr;
    void* dlut_ptr = nullptr;
    cudaGetSymbolAddress(&acc_ptr, g_acc);
    cudaGetSymbolAddress(&dlut_ptr, g_dlut);

    // acc -> 0 (sums+counts), dlut -> 0xFFFFFFFF (atomicMin identity; depth
    // bits are < 0x3F800000 so any real splat wins).
    cudaMemsetAsync(acc_ptr, 0, (size_t)NN * sizeof(float4), 0);
    cudaMemsetAsync(dlut_ptr, 0xFF, (size_t)NN * sizeof(unsigned int), 0);

    const int TPB = 256;
    const int blocks = NN / 4 / TPB;  // NN = 4M, exact
    zmin_kernel<<<blocks, TPB, 0, 0>>>(flow, depth);
    splat_kernel<<<blocks, TPB, 0, 0>>>(obj, flow, depth);
    normalize_kernel<<<blocks, TPB, 0, 0>>>(out);
}